// round 15
// baseline (speedup 1.0000x reference)
#include <cuda_runtime.h>
#include <cuda_fp16.h>
#include <math.h>
#include <stdint.h>

#define TT 2048
#define CC 1024
#define HH 16
#define DD 64
#define BBATCH 2
#define MTOT (BBATCH * TT)   // 4096
#define FFDIM (4 * CC)       // 4096
#define LOG2E 1.4426950408889634f

// -------- scratch (alloc-free) --------
__device__ __half g_h1[MTOT * CC];
__device__ __half g_q[MTOT * CC];     // (b,h,t,d), pre-scaled by 0.125*log2e
__device__ __half g_k[MTOT * CC];     // (b,h,t,d)
__device__ __half g_v[MTOT * CC];     // (b,h,d,t) transposed
__device__ __half g_attn[MTOT * CC];
__device__ float  g_x1[MTOT * CC];
__device__ __half g_h2[MTOT * CC];
__device__ __half g_ff1[MTOT * FFDIM];
// transposed fp16 weights [N][K]
__device__ __half g_wpt[CC * CC];
__device__ __half g_w1t[FFDIM * CC];
__device__ __half g_w2t[CC * FFDIM];
__device__ __half g_wqt[HH * DD * CC];
__device__ __half g_wkt[HH * DD * CC];
__device__ __half g_wvt[HH * DD * CC];

// -------- helpers --------
__device__ __forceinline__ void mma_f16(float* c, const unsigned* a, const unsigned* b) {
    asm volatile(
        "mma.sync.aligned.m16n8k16.row.col.f32.f16.f16.f32 "
        "{%0,%1,%2,%3}, {%4,%5,%6,%7}, {%8,%9}, {%0,%1,%2,%3};"
        : "+f"(c[0]), "+f"(c[1]), "+f"(c[2]), "+f"(c[3])
        : "r"(a[0]), "r"(a[1]), "r"(a[2]), "r"(a[3]), "r"(b[0]), "r"(b[1]));
}
__device__ __forceinline__ void cp16(uint32_t s, const void* g) {
    asm volatile("cp.async.ca.shared.global [%0], [%1], 16;" :: "r"(s), "l"(g));
}
__device__ __forceinline__ void cp_commit() { asm volatile("cp.async.commit_group;"); }
template <int N>
__device__ __forceinline__ void cp_wait() { asm volatile("cp.async.wait_group %0;" :: "n"(N)); }
__device__ __forceinline__ void ldsm4(unsigned& r0, unsigned& r1, unsigned& r2, unsigned& r3,
                                      uint32_t a) {
    asm volatile("ldmatrix.sync.aligned.m8n8.x4.shared.b16 {%0,%1,%2,%3}, [%4];"
                 : "=r"(r0), "=r"(r1), "=r"(r2), "=r"(r3) : "r"(a));
}
// packed fp16x2 2^x
__device__ __forceinline__ unsigned h2ex2(unsigned a) {
    unsigned d;
    asm("ex2.approx.f16x2 %0, %1;" : "=r"(d) : "r"(a));
    return d;
}
// 128B-pitch tile (64 halves/row): seg 0..7, conflict-free swizzle
__device__ __forceinline__ uint32_t swz(uint32_t r, uint32_t seg) {
    return r * 128 + ((seg ^ (r & 7)) * 16);
}

// ============================================================
// Merged big-weight transpose fp32 -> fp16 [N][K]:
// blocks [0,1024): w_proj; [1024,5120): w1; [5120,9216): w2
// ============================================================
__global__ void transpose_big(const float* __restrict__ wp, const float* __restrict__ w1,
                              const float* __restrict__ w2, __half* __restrict__ owp,
                              __half* __restrict__ ow1, __half* __restrict__ ow2) {
    __shared__ float t[32][33];
    int bid = blockIdx.x;
    const float* in;
    __half* out;
    int R, Cc, tile;
    if (bid < 1024)      { in = wp; out = owp; R = CC;    Cc = CC;    tile = bid; }
    else if (bid < 5120) { in = w1; out = ow1; R = CC;    Cc = FFDIM; tile = bid - 1024; }
    else                 { in = w2; out = ow2; R = FFDIM; Cc = CC;    tile = bid - 5120; }
    int nx = Cc >> 5;
    int c0 = (tile % nx) * 32, r0 = (tile / nx) * 32;
    int x = threadIdx.x, y = threadIdx.y;
    #pragma unroll
    for (int i = 0; i < 32; i += 8)
        t[y + i][x] = in[(size_t)(r0 + y + i) * Cc + c0 + x];
    __syncthreads();
    #pragma unroll
    for (int i = 0; i < 32; i += 8)
        out[(size_t)(c0 + y + i) * R + r0 + x] = __float2half(t[x][y + i]);
}

// Merged QKV weight transpose: z = which*HH + head
__global__ void transpose_qkv(const float* __restrict__ wq, const float* __restrict__ wk,
                              const float* __restrict__ wv, __half* __restrict__ oq,
                              __half* __restrict__ ok, __half* __restrict__ ov) {
    __shared__ float t[32][33];
    int which = blockIdx.z / HH, hd = blockIdx.z % HH;
    const float* ip = (which == 0 ? wq : (which == 1 ? wk : wv)) + (size_t)hd * CC * DD;
    __half* op = (which == 0 ? oq : (which == 1 ? ok : ov)) + (size_t)hd * CC * DD;
    int c0 = blockIdx.x * 32, r0 = blockIdx.y * 32;
    int x = threadIdx.x, y = threadIdx.y;
    #pragma unroll
    for (int i = 0; i < 32; i += 8)
        t[y + i][x] = ip[(size_t)(r0 + y + i) * DD + c0 + x];
    __syncthreads();
    #pragma unroll
    for (int i = 0; i < 32; i += 8)
        op[(size_t)(c0 + y + i) * CC + r0 + x] = __float2half(t[x][y + i]);
}

// ============================================================
// LayerNorm: fp32 in -> fp16 out
// ============================================================
__global__ void ln_kernel(const float* __restrict__ x, const float* __restrict__ g,
                          const float* __restrict__ b, __half* __restrict__ out) {
    __shared__ float red[8];
    __shared__ float s_mu, s_rstd;
    int row = blockIdx.x;
    int tid = threadIdx.x;
    const float* xr = x + (size_t)row * CC;

    float v0 = xr[tid], v1 = xr[tid + 256], v2 = xr[tid + 512], v3 = xr[tid + 768];
    float s = v0 + v1 + v2 + v3;
    #pragma unroll
    for (int o = 16; o > 0; o >>= 1) s += __shfl_xor_sync(0xffffffffu, s, o);
    if ((tid & 31) == 0) red[tid >> 5] = s;
    __syncthreads();
    if (tid == 0) {
        float t = 0.f;
        #pragma unroll
        for (int i = 0; i < 8; i++) t += red[i];
        s_mu = t * (1.0f / CC);
    }
    __syncthreads();
    float mu = s_mu;
    float d0 = v0 - mu, d1 = v1 - mu, d2 = v2 - mu, d3 = v3 - mu;
    float s2 = d0 * d0 + d1 * d1 + d2 * d2 + d3 * d3;
    #pragma unroll
    for (int o = 16; o > 0; o >>= 1) s2 += __shfl_xor_sync(0xffffffffu, s2, o);
    __syncthreads();
    if ((tid & 31) == 0) red[tid >> 5] = s2;
    __syncthreads();
    if (tid == 0) {
        float t = 0.f;
        #pragma unroll
        for (int i = 0; i < 8; i++) t += red[i];
        s_rstd = rsqrtf(t * (1.0f / CC) + 1e-5f);
    }
    __syncthreads();
    float rstd = s_rstd;
    __half* orow = out + (size_t)row * CC;
    orow[tid]       = __float2half(d0 * rstd * g[tid]       + b[tid]);
    orow[tid + 256] = __float2half(d1 * rstd * g[tid + 256] + b[tid + 256]);
    orow[tid + 512] = __float2half(d2 * rstd * g[tid + 512] + b[tid + 512]);
    orow[tid + 768] = __float2half(d3 * rstd * g[tid + 768] + b[tid + 768]);
}

// ============================================================
// fp16 GEMM, 3-stage cp.async, ONE barrier per k-iter.
// BM=BN=128, BK=64 halves, 256 thr = 8 warps (2x4), warp 64x32.
// smem: 3 stages x (A+B) x 16KB = 96KB.
// ============================================================
#define GT_BYTES (128 * 128)
#define G_SMEM (6 * GT_BYTES)   // 98304

template <bool RELU, bool HALFOUT>
__global__ __launch_bounds__(256) void gemm_f16(
    const __half* __restrict__ A, const __half* __restrict__ Bt,
    const float* __restrict__ bias, const float* __restrict__ res,
    void* __restrict__ Cout, int M, int N, int K) {
    extern __shared__ char smx[];
    uint32_t sA = (uint32_t)__cvta_generic_to_shared(smx);
    uint32_t sB = sA + 3 * GT_BYTES;

    int tid = threadIdx.x;
    int warp = tid >> 5, lane = tid & 31;
    int g = lane >> 2, t = lane & 3;
    int wm = (warp >> 2) * 64, wn = (warp & 3) * 32;
    int m0 = blockIdx.y * 128, n0 = blockIdx.x * 128;

    float acc[4][4][4] = {};
    int a_row = wm + (lane & 7) + ((lane >> 3) & 1) * 8;
    int a_sg = lane >> 4;
    int b_row = wn + (lane & 7) + (lane >> 4) * 8;
    int b_sg = (lane >> 3) & 1;

    auto pre = [&](int st, int k0) {
        #pragma unroll
        for (int i = 0; i < 4; i++) {
            int ch = tid + 256 * i;
            int r = ch >> 3, c = ch & 7;
            cp16(sA + st * GT_BYTES + swz(r, c), A + (size_t)(m0 + r) * K + k0 + c * 8);
        }
        #pragma unroll
        for (int i = 0; i < 4; i++) {
            int ch = tid + 256 * i;
            int r = ch >> 3, c = ch & 7;
            cp16(sB + st * GT_BYTES + swz(r, c), Bt + (size_t)(n0 + r) * K + k0 + c * 8);
        }
        cp_commit();
    };

    pre(0, 0);
    pre(1, 64);
    int nk = K >> 6;
    int st = 0;
    for (int kk = 0; kk < nk; kk++) {
        if (kk + 1 < nk) cp_wait<1>(); else cp_wait<0>();
        __syncthreads();
        if (kk + 2 < nk) {
            int st2 = st + 2; if (st2 >= 3) st2 -= 3;
            pre(st2, (kk + 2) << 6);
        }

        uint32_t sAs = sA + st * GT_BYTES;
        uint32_t sBs = sB + st * GT_BYTES;
        #pragma unroll
        for (int ks = 0; ks < 4; ks++) {
            unsigned af[4][4];
            #pragma unroll
            for (int mi = 0; mi < 4; mi++)
                ldsm4(af[mi][0], af[mi][1], af[mi][2], af[mi][3],
                      sAs + swz(a_row + mi * 16, 2 * ks + a_sg));
            #pragma unroll
            for (int nj2 = 0; nj2 < 2; nj2++) {
                unsigned r0, r1, r2, r3;
                ldsm4(r0, r1, r2, r3, sBs + swz(b_row + nj2 * 16, 2 * ks + b_sg));
                unsigned b0[2] = {r0, r1}, b1[2] = {r2, r3};
                #pragma unroll
                for (int mi = 0; mi < 4; mi++) {
                    mma_f16(acc[mi][2 * nj2],     af[mi], b0);
                    mma_f16(acc[mi][2 * nj2 + 1], af[mi], b1);
                }
            }
        }
        if (++st == 3) st = 0;
    }

    #pragma unroll
    for (int mi = 0; mi < 4; mi++) {
        #pragma unroll
        for (int nj = 0; nj < 4; nj++) {
            int c = n0 + wn + nj * 8 + 2 * t;
            int r0 = m0 + wm + mi * 16 + g;
            int r1 = r0 + 8;
            float2 o0 = {acc[mi][nj][0], acc[mi][nj][1]};
            float2 o1 = {acc[mi][nj][2], acc[mi][nj][3]};
            if (bias) {
                float2 bv = *(const float2*)(bias + c);
                o0.x += bv.x; o0.y += bv.y; o1.x += bv.x; o1.y += bv.y;
            }
            if (res) {
                float2 ra = *(const float2*)(res + (size_t)r0 * N + c);
                float2 rb = *(const float2*)(res + (size_t)r1 * N + c);
                o0.x += ra.x; o0.y += ra.y; o1.x += rb.x; o1.y += rb.y;
            }
            if (RELU) {
                o0.x = fmaxf(o0.x, 0.f); o0.y = fmaxf(o0.y, 0.f);
                o1.x = fmaxf(o1.x, 0.f); o1.y = fmaxf(o1.y, 0.f);
            }
            if (HALFOUT) {
                __half* C = (__half*)Cout;
                *(__half2*)(C + (size_t)r0 * N + c) = __floats2half2_rn(o0.x, o0.y);
                *(__half2*)(C + (size_t)r1 * N + c) = __floats2half2_rn(o1.x, o1.y);
            } else {
                float* C = (float*)Cout;
                *(float2*)(C + (size_t)r0 * N + c) = o0;
                *(float2*)(C + (size_t)r1 * N + c) = o1;
            }
        }
    }
}

// ============================================================
// Merged QKV GEMM, 3-stage. Q scale = 0.125*log2e.
// ============================================================
__global__ __launch_bounds__(256) void qkv_f16(
    const __half* __restrict__ h, const __half* __restrict__ wqt,
    const __half* __restrict__ wkt, const __half* __restrict__ wvt,
    __half* __restrict__ q, __half* __restrict__ k, __half* __restrict__ v) {
    extern __shared__ char smx[];
    uint32_t sA = (uint32_t)__cvta_generic_to_shared(smx);
    uint32_t sB = sA + 3 * GT_BYTES;

    int which = blockIdx.y >> 3;
    int hp = blockIdx.y & 7;
    const __half* Wt = (which == 0 ? wqt : (which == 1 ? wkt : wvt));
    __half* O = (which == 0 ? q : (which == 1 ? k : v));
    float oscale = (which == 0) ? 0.125f * LOG2E : 1.0f;

    int tid = threadIdx.x;
    int warp = tid >> 5, lane = tid & 31;
    int g = lane >> 2, t = lane & 3;
    int wm = (warp >> 2) * 64, wn = (warp & 3) * 32;
    int m0 = blockIdx.x * 128;

    float acc[4][4][4] = {};
    int a_row = wm + (lane & 7) + ((lane >> 3) & 1) * 8;
    int a_sg = lane >> 4;
    int b_row = wn + (lane & 7) + (lane >> 4) * 8;
    int b_sg = (lane >> 3) & 1;

    auto pre = [&](int st, int k0) {
        #pragma unroll
        for (int i = 0; i < 4; i++) {
            int ch = tid + 256 * i;
            int r = ch >> 3, c = ch & 7;
            cp16(sA + st * GT_BYTES + swz(r, c), h + (size_t)(m0 + r) * CC + k0 + c * 8);
        }
        #pragma unroll
        for (int i = 0; i < 4; i++) {
            int ch = tid + 256 * i;
            int r = ch >> 3, c = ch & 7;
            cp16(sB + st * GT_BYTES + swz(r, c),
                 Wt + (size_t)(hp * 128 + r) * CC + k0 + c * 8);
        }
        cp_commit();
    };

    pre(0, 0);
    pre(1, 64);
    int nk = CC >> 6;
    int st = 0;
    for (int kk = 0; kk < nk; kk++) {
        if (kk + 1 < nk) cp_wait<1>(); else cp_wait<0>();
        __syncthreads();
        if (kk + 2 < nk) {
            int st2 = st + 2; if (st2 >= 3) st2 -= 3;
            pre(st2, (kk + 2) << 6);
        }

        uint32_t sAs = sA + st * GT_BYTES;
        uint32_t sBs = sB + st * GT_BYTES;
        #pragma unroll
        for (int ks = 0; ks < 4; ks++) {
            unsigned af[4][4];
            #pragma unroll
            for (int mi = 0; mi < 4; mi++)
                ldsm4(af[mi][0], af[mi][1], af[mi][2], af[mi][3],
                      sAs + swz(a_row + mi * 16, 2 * ks + a_sg));
            #pragma unroll
            for (int nj2 = 0; nj2 < 2; nj2++) {
                unsigned r0, r1, r2, r3;
                ldsm4(r0, r1, r2, r3, sBs + swz(b_row + nj2 * 16, 2 * ks + b_sg));
                unsigned b0[2] = {r0, r1}, b1[2] = {r2, r3};
                #pragma unroll
                for (int mi = 0; mi < 4; mi++) {
                    mma_f16(acc[mi][2 * nj2],     af[mi], b0);
                    mma_f16(acc[mi][2 * nj2 + 1], af[mi], b1);
                }
            }
        }
        if (++st == 3) st = 0;
    }

    #pragma unroll
    for (int mi = 0; mi < 4; mi++) {
        #pragma unroll
        for (int nj = 0; nj < 4; nj++) {
            int c = wn + nj * 8 + 2 * t;
            int head = 2 * hp + (c >> 6);
            int d = c & 63;
            int m0r = m0 + wm + mi * 16 + g;
            int m1r = m0r + 8;
            int b0 = m0r >> 11, t0i = m0r & (TT - 1);
            int b1 = m1r >> 11, t1i = m1r & (TT - 1);
            float a0 = acc[mi][nj][0] * oscale, a1 = acc[mi][nj][1] * oscale;
            float a2 = acc[mi][nj][2] * oscale, a3 = acc[mi][nj][3] * oscale;
            if (which == 2) {
                size_t base0 = ((size_t)(b0 * HH + head) * DD);
                size_t base1 = ((size_t)(b1 * HH + head) * DD);
                O[(base0 + d)     * TT + t0i] = __float2half(a0);
                O[(base0 + d + 1) * TT + t0i] = __float2half(a1);
                O[(base1 + d)     * TT + t1i] = __float2half(a2);
                O[(base1 + d + 1) * TT + t1i] = __float2half(a3);
            } else {
                *(__half2*)(O + (((size_t)(b0 * HH + head) * TT + t0i) << 6) + d) =
                    __floats2half2_rn(a0, a1);
                *(__half2*)(O + (((size_t)(b1 * HH + head) * TT + t1i) << 6) + d) =
                    __floats2half2_rn(a2, a3);
            }
        }
    }
}

// ============================================================
// Flash attention (round-14 form, unchanged).
// ============================================================
__global__ __launch_bounds__(128) void attn_f16(
    const __half* __restrict__ Q, const __half* __restrict__ K,
    const __half* __restrict__ V, __half* __restrict__ out) {
    __shared__ __align__(128) char Qb[64 * 128];
    __shared__ __align__(128) char Kb[64 * 128];
    __shared__ __align__(128) char Vb[64 * 128];
    uint32_t sQ = (uint32_t)__cvta_generic_to_shared(Qb);
    uint32_t sK = (uint32_t)__cvta_generic_to_shared(Kb);
    uint32_t sV = (uint32_t)__cvta_generic_to_shared(Vb);

    int bh = blockIdx.y;
    int t0 = (int)(gridDim.x - 1 - blockIdx.x) * 64;
    const __half* Qp = Q + (size_t)bh * TT * DD;
    const __half* Kp = K + (size_t)bh * TT * DD;
    const __half* Vp = V + (size_t)bh * TT * DD;

    int tid = threadIdx.x;
    int warp = tid >> 5, lane = tid & 31;
    int g = lane >> 2, t = lane & 3;
    int wr = warp * 16;

    int fr_row = (lane & 7) + ((lane >> 3) & 1) * 8;
    int fr_sg = lane >> 4;
    int bn_row = (lane & 7) + (lane >> 4) * 8;
    int bn_sg = (lane >> 3) & 1;

    #pragma unroll
    for (int i = 0; i < 4; i++) {
        int ch = tid + 128 * i;
        int r = ch >> 3, c = ch & 7;
        cp16(sQ + swz(r, c), Qp + (size_t)(t0 + r) * DD + c * 8);
    }
    cp_commit();
    cp_wait<0>();
    __syncthreads();
    unsigned qa[4][4];
    #pragma unroll
    for (int ks = 0; ks < 4; ks++)
        ldsm4(qa[ks][0], qa[ks][1], qa[ks][2], qa[ks][3],
              sQ + swz(wr + fr_row, 2 * ks + fr_sg));
    __syncthreads();

    float m0r = -1e30f, m1r = -1e30f, l0 = 0.f, l1 = 0.f;
    float oacc[8][4] = {};

    int ntiles = t0 / 64 + 1;
    for (int it = 0; it < ntiles; it++) {
        int s0 = it * 64;
        #pragma unroll
        for (int i = 0; i < 4; i++) {
            int ch = tid + 128 * i;
            int r = ch >> 3, c = ch & 7;
            cp16(sK + swz(r, c), Kp + (size_t)(s0 + r) * DD + c * 8);
        }
        #pragma unroll
        for (int i = 0; i < 4; i++) {
            int ch = tid + 128 * i;
            int d = ch >> 3, c = ch & 7;
            cp16(sV + swz(d, c), Vp + (size_t)d * TT + s0 + c * 8);
        }
        cp_commit();
        cp_wait<0>();
        __syncthreads();

        float sacc[8][4] = {};
        #pragma unroll
        for (int ks = 0; ks < 4; ks++) {
            #pragma unroll
            for (int nj2 = 0; nj2 < 4; nj2++) {
                unsigned r0, r1, r2, r3;
                ldsm4(r0, r1, r2, r3, sK + swz(nj2 * 16 + bn_row, 2 * ks + bn_sg));
                unsigned b0[2] = {r0, r1}, b1[2] = {r2, r3};
                mma_f16(sacc[2 * nj2], qa[ks], b0);
                mma_f16(sacc[2 * nj2 + 1], qa[ks], b1);
            }
        }

        if (s0 == t0) {
            #pragma unroll
            for (int nj = 0; nj < 8; nj++) {
                int c0 = nj * 8 + 2 * t, c1 = c0 + 1;
                int r0 = wr + g, r1 = r0 + 8;
                if (c0 > r0) sacc[nj][0] = -1e30f;
                if (c1 > r0) sacc[nj][1] = -1e30f;
                if (c0 > r1) sacc[nj][2] = -1e30f;
                if (c1 > r1) sacc[nj][3] = -1e30f;
            }
        }

        float mt0 = -1e30f, mt1 = -1e30f;
        #pragma unroll
        for (int nj = 0; nj < 8; nj++) {
            mt0 = fmaxf(mt0, fmaxf(sacc[nj][0], sacc[nj][1]));
            mt1 = fmaxf(mt1, fmaxf(sacc[nj][2], sacc[nj][3]));
        }
        #pragma unroll
        for (int o = 1; o <= 2; o <<= 1) {
            mt0 = fmaxf(mt0, __shfl_xor_sync(0xffffffffu, mt0, o));
            mt1 = fmaxf(mt1, __shfl_xor_sync(0xffffffffu, mt1, o));
        }
        float mn0 = fmaxf(m0r, mt0), mn1 = fmaxf(m1r, mt1);
        float sc0 = exp2f(m0r - mn0), sc1 = exp2f(m1r - mn1);
        float sum0 = 0.f, sum1 = 0.f;
        int pr0 = wr + g, pr1 = wr + 8 + g;
        #pragma unroll
        for (int nj = 0; nj < 8; nj++) {
            __half2 x0 = __floats2half2_rn(sacc[nj][0] - mn0, sacc[nj][1] - mn0);
            __half2 x1 = __floats2half2_rn(sacc[nj][2] - mn1, sacc[nj][3] - mn1);
            unsigned e0 = h2ex2(*(unsigned*)&x0);
            unsigned e1 = h2ex2(*(unsigned*)&x1);
            float2 f0 = __half22float2(*(__half2*)&e0);
            float2 f1 = __half22float2(*(__half2*)&e1);
            sum0 += f0.x + f0.y;
            sum1 += f1.x + f1.y;
            *(unsigned*)(Qb + pr0 * 128 + ((nj ^ (pr0 & 7)) * 8 + 2 * t) * 2) = e0;
            *(unsigned*)(Qb + pr1 * 128 + ((nj ^ (pr1 & 7)) * 8 + 2 * t) * 2) = e1;
        }
        #pragma unroll
        for (int o = 1; o <= 2; o <<= 1) {
            sum0 += __shfl_xor_sync(0xffffffffu, sum0, o);
            sum1 += __shfl_xor_sync(0xffffffffu, sum1, o);
        }
        l0 = l0 * sc0 + sum0;
        l1 = l1 * sc1 + sum1;
        m0r = mn0; m1r = mn1;
        #pragma unroll
        for (int nj = 0; nj < 8; nj++) {
            oacc[nj][0] *= sc0; oacc[nj][1] *= sc0;
            oacc[nj][2] *= sc1; oacc[nj][3] *= sc1;
        }
        __syncwarp();

        #pragma unroll
        for (int j = 0; j < 4; j++) {
            unsigned pa[4];
            ldsm4(pa[0], pa[1], pa[2], pa[3], sQ + swz(wr + fr_row, 2 * j + fr_sg));
            #pragma unroll
            for (int nj2 = 0; nj2 < 4; nj2++) {
                unsigned r0, r1, r2, r3;
                ldsm4(r0, r1, r2, r3, sV + swz(nj2 * 16 + bn_row, 2 * j + bn_sg));
                unsigned b0[2] = {r0, r1}, b1[2] = {r2, r3};
                mma_f16(oacc[2 * nj2], pa, b0);
                mma_f16(oacc[2 * nj2 + 1], pa, b1);
            }
        }
        __syncthreads();
    }

    float inv0 = 1.f / l0, inv1 = 1.f / l1;
    int b = bh >> 4, hh = bh & 15;
    int tr0 = t0 + wr + g, tr1 = tr0 + 8;
    #pragma unroll
    for (int nj = 0; nj < 8; nj++) {
        int c = hh * DD + nj * 8 + 2 * t;
        *(__half2*)(out + (size_t)(b * TT + tr0) * CC + c) =
            __floats2half2_rn(oacc[nj][0] * inv0, oacc[nj][1] * inv0);
        *(__half2*)(out + (size_t)(b * TT + tr1) * CC + c) =
            __floats2half2_rn(oacc[nj][2] * inv1, oacc[nj][3] * inv1);
    }
}

// ============================================================
// launch
// ============================================================
extern "C" void kernel_launch(void* const* d_in, const int* in_sizes, int n_in,
                              void* d_out, int out_size) {
    const float* x      = (const float*)d_in[0];
    const float* wq     = (const float*)d_in[1];
    const float* wk     = (const float*)d_in[2];
    const float* wv     = (const float*)d_in[3];
    const float* w_proj = (const float*)d_in[4];
    const float* b_proj = (const float*)d_in[5];
    const float* w1     = (const float*)d_in[6];
    const float* b1     = (const float*)d_in[7];
    const float* w2     = (const float*)d_in[8];
    const float* b2     = (const float*)d_in[9];
    const float* g1     = (const float*)d_in[10];
    const float* be1    = (const float*)d_in[11];
    const float* g2     = (const float*)d_in[12];
    const float* be2    = (const float*)d_in[13];
    float* out = (float*)d_out;

    __half *h1, *q, *k, *v, *attn, *h2, *ff1;
    __half *wpt, *w1t, *w2t, *wqt, *wkt, *wvt;
    float *x1;
    cudaGetSymbolAddress((void**)&h1, g_h1);
    cudaGetSymbolAddress((void**)&q, g_q);
    cudaGetSymbolAddress((void**)&k, g_k);
    cudaGetSymbolAddress((void**)&v, g_v);
    cudaGetSymbolAddress((void**)&attn, g_attn);
    cudaGetSymbolAddress((void**)&x1, g_x1);
    cudaGetSymbolAddress((void**)&h2, g_h2);
    cudaGetSymbolAddress((void**)&ff1, g_ff1);
    cudaGetSymbolAddress((void**)&wpt, g_wpt);
    cudaGetSymbolAddress((void**)&w1t, g_w1t);
    cudaGetSymbolAddress((void**)&w2t, g_w2t);
    cudaGetSymbolAddress((void**)&wqt, g_wqt);
    cudaGetSymbolAddress((void**)&wkt, g_wkt);
    cudaGetSymbolAddress((void**)&wvt, g_wvt);

    cudaFuncSetAttribute(gemm_f16<false, false>, cudaFuncAttributeMaxDynamicSharedMemorySize, G_SMEM);
    cudaFuncSetAttribute(gemm_f16<true, true>,   cudaFuncAttributeMaxDynamicSharedMemorySize, G_SMEM);
    cudaFuncSetAttribute(qkv_f16, cudaFuncAttributeMaxDynamicSharedMemorySize, G_SMEM);

    // 0. weight transposes -> fp16 [N][K]
    transpose_big<<<9216, dim3(32, 8)>>>(w_proj, w1, w2, wpt, w1t, w2t);
    transpose_qkv<<<dim3(DD / 32, CC / 32, 3 * HH), dim3(32, 8)>>>(wq, wk, wv, wqt, wkt, wvt);
    // 1. LN1 -> fp16
    ln_kernel<<<MTOT, 256>>>(x, g1, be1, h1);
    // 2. QKV (merged; q pre-scaled by 0.125*log2e, v transposed)
    qkv_f16<<<dim3(MTOT / 128, 3 * (HH / 2)), 256, G_SMEM>>>(h1, wqt, wkt, wvt, q, k, v);
    // 3. attention -> fp16
    attn_f16<<<dim3(TT / 64, BBATCH * HH), 128>>>(q, k, v, attn);
    // 4. proj + bias + residual -> x1 (fp32)
    gemm_f16<false, false><<<dim3(CC / 128, MTOT / 128), 256, G_SMEM>>>(
        attn, wpt, b_proj, x, x1, MTOT, CC, CC);
    // 5. LN2 -> fp16
    ln_kernel<<<MTOT, 256>>>(x1, g2, be2, h2);
    // 6. FF1 + bias + relu -> fp16
    gemm_f16<true, true><<<dim3(FFDIM / 128, MTOT / 128), 256, G_SMEM>>>(
        h2, w1t, b1, nullptr, ff1, MTOT, FFDIM, CC);
    // 7. FF2 + bias + residual -> out (fp32)
    gemm_f16<false, false><<<dim3(CC / 128, MTOT / 128), 256, G_SMEM>>>(
        ff1, w2t, b2, x1, out, MTOT, CC, FFDIM);
}

// round 16
// speedup vs baseline: 1.0275x; 1.0275x over previous
#include <cuda_runtime.h>
#include <cuda_fp16.h>
#include <math.h>
#include <stdint.h>

#define TT 2048
#define CC 1024
#define HH 16
#define DD 64
#define BBATCH 2
#define MTOT (BBATCH * TT)   // 4096
#define FFDIM (4 * CC)       // 4096
#define LOG2E 1.4426950408889634f

// -------- scratch (alloc-free) --------
__device__ __half g_h1[MTOT * CC];
__device__ __half g_q[MTOT * CC];     // (b,h,t,d), pre-scaled by 0.125*log2e
__device__ __half g_k[MTOT * CC];     // (b,h,t,d)
__device__ __half g_v[MTOT * CC];     // (b,h,d,t) transposed
__device__ __half g_attn[MTOT * CC];
__device__ float  g_x1[MTOT * CC];
__device__ __half g_h2[MTOT * CC];
__device__ __half g_ff1[MTOT * FFDIM];
// transposed fp16 weights [N][K]
__device__ __half g_wpt[CC * CC];
__device__ __half g_w1t[FFDIM * CC];
__device__ __half g_w2t[CC * FFDIM];
__device__ __half g_wqt[HH * DD * CC];
__device__ __half g_wkt[HH * DD * CC];
__device__ __half g_wvt[HH * DD * CC];

// -------- helpers --------
__device__ __forceinline__ void mma_f16(float* c, const unsigned* a, const unsigned* b) {
    asm volatile(
        "mma.sync.aligned.m16n8k16.row.col.f32.f16.f16.f32 "
        "{%0,%1,%2,%3}, {%4,%5,%6,%7}, {%8,%9}, {%0,%1,%2,%3};"
        : "+f"(c[0]), "+f"(c[1]), "+f"(c[2]), "+f"(c[3])
        : "r"(a[0]), "r"(a[1]), "r"(a[2]), "r"(a[3]), "r"(b[0]), "r"(b[1]));
}
__device__ __forceinline__ void cp16(uint32_t s, const void* g) {
    asm volatile("cp.async.ca.shared.global [%0], [%1], 16;" :: "r"(s), "l"(g));
}
__device__ __forceinline__ void cp_commit() { asm volatile("cp.async.commit_group;"); }
template <int N>
__device__ __forceinline__ void cp_wait() { asm volatile("cp.async.wait_group %0;" :: "n"(N)); }
__device__ __forceinline__ void ldsm4(unsigned& r0, unsigned& r1, unsigned& r2, unsigned& r3,
                                      uint32_t a) {
    asm volatile("ldmatrix.sync.aligned.m8n8.x4.shared.b16 {%0,%1,%2,%3}, [%4];"
                 : "=r"(r0), "=r"(r1), "=r"(r2), "=r"(r3) : "r"(a));
}
// packed fp16x2 2^x
__device__ __forceinline__ unsigned h2ex2(unsigned a) {
    unsigned d;
    asm("ex2.approx.f16x2 %0, %1;" : "=r"(d) : "r"(a));
    return d;
}
// 128B-pitch tile (64 halves/row): seg 0..7, conflict-free swizzle
__device__ __forceinline__ uint32_t swz(uint32_t r, uint32_t seg) {
    return r * 128 + ((seg ^ (r & 7)) * 16);
}

// ============================================================
// Merged big-weight transpose fp32 -> fp16 [N][K]
// ============================================================
__global__ void transpose_big(const float* __restrict__ wp, const float* __restrict__ w1,
                              const float* __restrict__ w2, __half* __restrict__ owp,
                              __half* __restrict__ ow1, __half* __restrict__ ow2) {
    __shared__ float t[32][33];
    int bid = blockIdx.x;
    const float* in;
    __half* out;
    int R, Cc, tile;
    if (bid < 1024)      { in = wp; out = owp; R = CC;    Cc = CC;    tile = bid; }
    else if (bid < 5120) { in = w1; out = ow1; R = CC;    Cc = FFDIM; tile = bid - 1024; }
    else                 { in = w2; out = ow2; R = FFDIM; Cc = CC;    tile = bid - 5120; }
    int nx = Cc >> 5;
    int c0 = (tile % nx) * 32, r0 = (tile / nx) * 32;
    int x = threadIdx.x, y = threadIdx.y;
    #pragma unroll
    for (int i = 0; i < 32; i += 8)
        t[y + i][x] = in[(size_t)(r0 + y + i) * Cc + c0 + x];
    __syncthreads();
    #pragma unroll
    for (int i = 0; i < 32; i += 8)
        out[(size_t)(c0 + y + i) * R + r0 + x] = __float2half(t[x][y + i]);
}

// Merged QKV weight transpose: z = which*HH + head
__global__ void transpose_qkv(const float* __restrict__ wq, const float* __restrict__ wk,
                              const float* __restrict__ wv, __half* __restrict__ oq,
                              __half* __restrict__ ok, __half* __restrict__ ov) {
    __shared__ float t[32][33];
    int which = blockIdx.z / HH, hd = blockIdx.z % HH;
    const float* ip = (which == 0 ? wq : (which == 1 ? wk : wv)) + (size_t)hd * CC * DD;
    __half* op = (which == 0 ? oq : (which == 1 ? ok : ov)) + (size_t)hd * CC * DD;
    int c0 = blockIdx.x * 32, r0 = blockIdx.y * 32;
    int x = threadIdx.x, y = threadIdx.y;
    #pragma unroll
    for (int i = 0; i < 32; i += 8)
        t[y + i][x] = ip[(size_t)(r0 + y + i) * DD + c0 + x];
    __syncthreads();
    #pragma unroll
    for (int i = 0; i < 32; i += 8)
        op[(size_t)(c0 + y + i) * CC + r0 + x] = __float2half(t[x][y + i]);
}

// ============================================================
// LayerNorm: fp32 in -> fp16 out
// ============================================================
__global__ void ln_kernel(const float* __restrict__ x, const float* __restrict__ g,
                          const float* __restrict__ b, __half* __restrict__ out) {
    __shared__ float red[8];
    __shared__ float s_mu, s_rstd;
    int row = blockIdx.x;
    int tid = threadIdx.x;
    const float* xr = x + (size_t)row * CC;

    float v0 = xr[tid], v1 = xr[tid + 256], v2 = xr[tid + 512], v3 = xr[tid + 768];
    float s = v0 + v1 + v2 + v3;
    #pragma unroll
    for (int o = 16; o > 0; o >>= 1) s += __shfl_xor_sync(0xffffffffu, s, o);
    if ((tid & 31) == 0) red[tid >> 5] = s;
    __syncthreads();
    if (tid == 0) {
        float t = 0.f;
        #pragma unroll
        for (int i = 0; i < 8; i++) t += red[i];
        s_mu = t * (1.0f / CC);
    }
    __syncthreads();
    float mu = s_mu;
    float d0 = v0 - mu, d1 = v1 - mu, d2 = v2 - mu, d3 = v3 - mu;
    float s2 = d0 * d0 + d1 * d1 + d2 * d2 + d3 * d3;
    #pragma unroll
    for (int o = 16; o > 0; o >>= 1) s2 += __shfl_xor_sync(0xffffffffu, s2, o);
    __syncthreads();
    if ((tid & 31) == 0) red[tid >> 5] = s2;
    __syncthreads();
    if (tid == 0) {
        float t = 0.f;
        #pragma unroll
        for (int i = 0; i < 8; i++) t += red[i];
        s_rstd = rsqrtf(t * (1.0f / CC) + 1e-5f);
    }
    __syncthreads();
    float rstd = s_rstd;
    __half* orow = out + (size_t)row * CC;
    orow[tid]       = __float2half(d0 * rstd * g[tid]       + b[tid]);
    orow[tid + 256] = __float2half(d1 * rstd * g[tid + 256] + b[tid + 256]);
    orow[tid + 512] = __float2half(d2 * rstd * g[tid + 512] + b[tid + 512]);
    orow[tid + 768] = __float2half(d3 * rstd * g[tid + 768] + b[tid + 768]);
}

// ============================================================
// fp16 GEMM (round-14 2-stage form — confirmed best)
// ============================================================
#define GT_BYTES (128 * 128)
#define G_SMEM (4 * GT_BYTES)

template <bool RELU, bool HALFOUT>
__global__ __launch_bounds__(256) void gemm_f16(
    const __half* __restrict__ A, const __half* __restrict__ Bt,
    const float* __restrict__ bias, const float* __restrict__ res,
    void* __restrict__ Cout, int M, int N, int K) {
    extern __shared__ char smx[];
    uint32_t sA = (uint32_t)__cvta_generic_to_shared(smx);
    uint32_t sB = sA + 2 * GT_BYTES;

    int tid = threadIdx.x;
    int warp = tid >> 5, lane = tid & 31;
    int g = lane >> 2, t = lane & 3;
    int wm = (warp >> 2) * 64, wn = (warp & 3) * 32;
    int m0 = blockIdx.y * 128, n0 = blockIdx.x * 128;

    float acc[4][4][4] = {};
    int a_row = wm + (lane & 7) + ((lane >> 3) & 1) * 8;
    int a_sg = lane >> 4;
    int b_row = wn + (lane & 7) + (lane >> 4) * 8;
    int b_sg = (lane >> 3) & 1;

    auto pre = [&](int st, int k0) {
        #pragma unroll
        for (int i = 0; i < 4; i++) {
            int ch = tid + 256 * i;
            int r = ch >> 3, c = ch & 7;
            cp16(sA + st * GT_BYTES + swz(r, c), A + (size_t)(m0 + r) * K + k0 + c * 8);
        }
        #pragma unroll
        for (int i = 0; i < 4; i++) {
            int ch = tid + 256 * i;
            int r = ch >> 3, c = ch & 7;
            cp16(sB + st * GT_BYTES + swz(r, c), Bt + (size_t)(n0 + r) * K + k0 + c * 8);
        }
        cp_commit();
    };

    pre(0, 0);
    int nk = K >> 6;
    for (int kk = 0; kk < nk; kk++) {
        int st = kk & 1;
        if (kk + 1 < nk) { pre(st ^ 1, (kk + 1) << 6); cp_wait<1>(); }
        else cp_wait<0>();
        __syncthreads();

        uint32_t sAs = sA + st * GT_BYTES;
        uint32_t sBs = sB + st * GT_BYTES;
        #pragma unroll
        for (int ks = 0; ks < 4; ks++) {
            unsigned af[4][4];
            #pragma unroll
            for (int mi = 0; mi < 4; mi++)
                ldsm4(af[mi][0], af[mi][1], af[mi][2], af[mi][3],
                      sAs + swz(a_row + mi * 16, 2 * ks + a_sg));
            #pragma unroll
            for (int nj2 = 0; nj2 < 2; nj2++) {
                unsigned r0, r1, r2, r3;
                ldsm4(r0, r1, r2, r3, sBs + swz(b_row + nj2 * 16, 2 * ks + b_sg));
                unsigned b0[2] = {r0, r1}, b1[2] = {r2, r3};
                #pragma unroll
                for (int mi = 0; mi < 4; mi++) {
                    mma_f16(acc[mi][2 * nj2],     af[mi], b0);
                    mma_f16(acc[mi][2 * nj2 + 1], af[mi], b1);
                }
            }
        }
        __syncthreads();
    }

    #pragma unroll
    for (int mi = 0; mi < 4; mi++) {
        #pragma unroll
        for (int nj = 0; nj < 4; nj++) {
            int c = n0 + wn + nj * 8 + 2 * t;
            int r0 = m0 + wm + mi * 16 + g;
            int r1 = r0 + 8;
            float2 o0 = {acc[mi][nj][0], acc[mi][nj][1]};
            float2 o1 = {acc[mi][nj][2], acc[mi][nj][3]};
            if (bias) {
                float2 bv = *(const float2*)(bias + c);
                o0.x += bv.x; o0.y += bv.y; o1.x += bv.x; o1.y += bv.y;
            }
            if (res) {
                float2 ra = *(const float2*)(res + (size_t)r0 * N + c);
                float2 rb = *(const float2*)(res + (size_t)r1 * N + c);
                o0.x += ra.x; o0.y += ra.y; o1.x += rb.x; o1.y += rb.y;
            }
            if (RELU) {
                o0.x = fmaxf(o0.x, 0.f); o0.y = fmaxf(o0.y, 0.f);
                o1.x = fmaxf(o1.x, 0.f); o1.y = fmaxf(o1.y, 0.f);
            }
            if (HALFOUT) {
                __half* C = (__half*)Cout;
                *(__half2*)(C + (size_t)r0 * N + c) = __floats2half2_rn(o0.x, o0.y);
                *(__half2*)(C + (size_t)r1 * N + c) = __floats2half2_rn(o1.x, o1.y);
            } else {
                float* C = (float*)Cout;
                *(float2*)(C + (size_t)r0 * N + c) = o0;
                *(float2*)(C + (size_t)r1 * N + c) = o1;
            }
        }
    }
}

// ============================================================
// Merged QKV GEMM (round-14 2-stage form; Q scale = 0.125*log2e)
// ============================================================
__global__ __launch_bounds__(256) void qkv_f16(
    const __half* __restrict__ h, const __half* __restrict__ wqt,
    const __half* __restrict__ wkt, const __half* __restrict__ wvt,
    __half* __restrict__ q, __half* __restrict__ k, __half* __restrict__ v) {
    extern __shared__ char smx[];
    uint32_t sA = (uint32_t)__cvta_generic_to_shared(smx);
    uint32_t sB = sA + 2 * GT_BYTES;

    int which = blockIdx.y >> 3;
    int hp = blockIdx.y & 7;
    const __half* Wt = (which == 0 ? wqt : (which == 1 ? wkt : wvt));
    __half* O = (which == 0 ? q : (which == 1 ? k : v));
    float oscale = (which == 0) ? 0.125f * LOG2E : 1.0f;

    int tid = threadIdx.x;
    int warp = tid >> 5, lane = tid & 31;
    int g = lane >> 2, t = lane & 3;
    int wm = (warp >> 2) * 64, wn = (warp & 3) * 32;
    int m0 = blockIdx.x * 128;

    float acc[4][4][4] = {};
    int a_row = wm + (lane & 7) + ((lane >> 3) & 1) * 8;
    int a_sg = lane >> 4;
    int b_row = wn + (lane & 7) + (lane >> 4) * 8;
    int b_sg = (lane >> 3) & 1;

    auto pre = [&](int st, int k0) {
        #pragma unroll
        for (int i = 0; i < 4; i++) {
            int ch = tid + 256 * i;
            int r = ch >> 3, c = ch & 7;
            cp16(sA + st * GT_BYTES + swz(r, c), h + (size_t)(m0 + r) * CC + k0 + c * 8);
        }
        #pragma unroll
        for (int i = 0; i < 4; i++) {
            int ch = tid + 256 * i;
            int r = ch >> 3, c = ch & 7;
            cp16(sB + st * GT_BYTES + swz(r, c),
                 Wt + (size_t)(hp * 128 + r) * CC + k0 + c * 8);
        }
        cp_commit();
    };

    pre(0, 0);
    int nk = CC >> 6;
    for (int kk = 0; kk < nk; kk++) {
        int st = kk & 1;
        if (kk + 1 < nk) { pre(st ^ 1, (kk + 1) << 6); cp_wait<1>(); }
        else cp_wait<0>();
        __syncthreads();

        uint32_t sAs = sA + st * GT_BYTES;
        uint32_t sBs = sB + st * GT_BYTES;
        #pragma unroll
        for (int ks = 0; ks < 4; ks++) {
            unsigned af[4][4];
            #pragma unroll
            for (int mi = 0; mi < 4; mi++)
                ldsm4(af[mi][0], af[mi][1], af[mi][2], af[mi][3],
                      sAs + swz(a_row + mi * 16, 2 * ks + a_sg));
            #pragma unroll
            for (int nj2 = 0; nj2 < 2; nj2++) {
                unsigned r0, r1, r2, r3;
                ldsm4(r0, r1, r2, r3, sBs + swz(b_row + nj2 * 16, 2 * ks + b_sg));
                unsigned b0[2] = {r0, r1}, b1[2] = {r2, r3};
                #pragma unroll
                for (int mi = 0; mi < 4; mi++) {
                    mma_f16(acc[mi][2 * nj2],     af[mi], b0);
                    mma_f16(acc[mi][2 * nj2 + 1], af[mi], b1);
                }
            }
        }
        __syncthreads();
    }

    #pragma unroll
    for (int mi = 0; mi < 4; mi++) {
        #pragma unroll
        for (int nj = 0; nj < 4; nj++) {
            int c = wn + nj * 8 + 2 * t;
            int head = 2 * hp + (c >> 6);
            int d = c & 63;
            int m0r = m0 + wm + mi * 16 + g;
            int m1r = m0r + 8;
            int b0 = m0r >> 11, t0i = m0r & (TT - 1);
            int b1 = m1r >> 11, t1i = m1r & (TT - 1);
            float a0 = acc[mi][nj][0] * oscale, a1 = acc[mi][nj][1] * oscale;
            float a2 = acc[mi][nj][2] * oscale, a3 = acc[mi][nj][3] * oscale;
            if (which == 2) {
                size_t base0 = ((size_t)(b0 * HH + head) * DD);
                size_t base1 = ((size_t)(b1 * HH + head) * DD);
                O[(base0 + d)     * TT + t0i] = __float2half(a0);
                O[(base0 + d + 1) * TT + t0i] = __float2half(a1);
                O[(base1 + d)     * TT + t1i] = __float2half(a2);
                O[(base1 + d + 1) * TT + t1i] = __float2half(a3);
            } else {
                *(__half2*)(O + (((size_t)(b0 * HH + head) * TT + t0i) << 6) + d) =
                    __floats2half2_rn(a0, a1);
                *(__half2*)(O + (((size_t)(b1 * HH + head) * TT + t1i) << 6) + d) =
                    __floats2half2_rn(a2, a3);
            }
        }
    }
}

// ============================================================
// Flash attention: round-14 math + DOUBLE-BUFFERED K/V tiles.
// smem: Q/P 16KB + 2x K 16KB + 2x V 16KB = 80KB (dynamic).
// ============================================================
#define ATT_SMEM (16384 * 5)   // 81920

__global__ __launch_bounds__(128) void attn_f16(
    const __half* __restrict__ Q, const __half* __restrict__ K,
    const __half* __restrict__ V, __half* __restrict__ out) {
    extern __shared__ char smx[];
    uint32_t sQ = (uint32_t)__cvta_generic_to_shared(smx);   // Q stage then P
    uint32_t sK0 = sQ + 16384;         // + st*16384
    uint32_t sV0 = sQ + 49152;         // + st*16384
    char* Pb = smx;

    int bh = blockIdx.y;
    int t0 = (int)(gridDim.x - 1 - blockIdx.x) * 64;
    const __half* Qp = Q + (size_t)bh * TT * DD;
    const __half* Kp = K + (size_t)bh * TT * DD;
    const __half* Vp = V + (size_t)bh * TT * DD;   // (d,t)

    int tid = threadIdx.x;
    int warp = tid >> 5, lane = tid & 31;
    int g = lane >> 2, t = lane & 3;
    int wr = warp * 16;

    int fr_row = (lane & 7) + ((lane >> 3) & 1) * 8;
    int fr_sg = lane >> 4;
    int bn_row = (lane & 7) + (lane >> 4) * 8;
    int bn_sg = (lane >> 3) & 1;

    // stage Q
    #pragma unroll
    for (int i = 0; i < 4; i++) {
        int ch = tid + 128 * i;
        int r = ch >> 3, c = ch & 7;
        cp16(sQ + swz(r, c), Qp + (size_t)(t0 + r) * DD + c * 8);
    }
    cp_commit();
    cp_wait<0>();
    __syncthreads();
    unsigned qa[4][4];
    #pragma unroll
    for (int ks = 0; ks < 4; ks++)
        ldsm4(qa[ks][0], qa[ks][1], qa[ks][2], qa[ks][3],
              sQ + swz(wr + fr_row, 2 * ks + fr_sg));
    __syncthreads();

    auto preKV = [&](int st, int s0) {
        #pragma unroll
        for (int i = 0; i < 4; i++) {
            int ch = tid + 128 * i;
            int r = ch >> 3, c = ch & 7;
            cp16(sK0 + st * 16384 + swz(r, c), Kp + (size_t)(s0 + r) * DD + c * 8);
        }
        #pragma unroll
        for (int i = 0; i < 4; i++) {
            int ch = tid + 128 * i;
            int d = ch >> 3, c = ch & 7;
            cp16(sV0 + st * 16384 + swz(d, c), Vp + (size_t)d * TT + s0 + c * 8);
        }
        cp_commit();
    };

    float m0r = -1e30f, m1r = -1e30f, l0 = 0.f, l1 = 0.f;
    float oacc[8][4] = {};

    int ntiles = t0 / 64 + 1;
    preKV(0, 0);
    for (int it = 0; it < ntiles; it++) {
        int s0 = it * 64;
        int st = it & 1;
        if (it + 1 < ntiles) { preKV(st ^ 1, s0 + 64); cp_wait<1>(); }
        else cp_wait<0>();
        __syncthreads();
        uint32_t sK = sK0 + st * 16384;
        uint32_t sV = sV0 + st * 16384;

        // S = Q @ K^T (log2 domain)
        float sacc[8][4] = {};
        #pragma unroll
        for (int ks = 0; ks < 4; ks++) {
            #pragma unroll
            for (int nj2 = 0; nj2 < 4; nj2++) {
                unsigned r0, r1, r2, r3;
                ldsm4(r0, r1, r2, r3, sK + swz(nj2 * 16 + bn_row, 2 * ks + bn_sg));
                unsigned b0[2] = {r0, r1}, b1[2] = {r2, r3};
                mma_f16(sacc[2 * nj2], qa[ks], b0);
                mma_f16(sacc[2 * nj2 + 1], qa[ks], b1);
            }
        }

        // causal mask (diagonal tile only)
        if (s0 == t0) {
            #pragma unroll
            for (int nj = 0; nj < 8; nj++) {
                int c0 = nj * 8 + 2 * t, c1 = c0 + 1;
                int r0 = wr + g, r1 = r0 + 8;
                if (c0 > r0) sacc[nj][0] = -1e30f;
                if (c1 > r0) sacc[nj][1] = -1e30f;
                if (c0 > r1) sacc[nj][2] = -1e30f;
                if (c1 > r1) sacc[nj][3] = -1e30f;
            }
        }

        // online softmax in log2 domain; probs via ex2.approx.f16x2
        float mt0 = -1e30f, mt1 = -1e30f;
        #pragma unroll
        for (int nj = 0; nj < 8; nj++) {
            mt0 = fmaxf(mt0, fmaxf(sacc[nj][0], sacc[nj][1]));
            mt1 = fmaxf(mt1, fmaxf(sacc[nj][2], sacc[nj][3]));
        }
        #pragma unroll
        for (int o = 1; o <= 2; o <<= 1) {
            mt0 = fmaxf(mt0, __shfl_xor_sync(0xffffffffu, mt0, o));
            mt1 = fmaxf(mt1, __shfl_xor_sync(0xffffffffu, mt1, o));
        }
        float mn0 = fmaxf(m0r, mt0), mn1 = fmaxf(m1r, mt1);
        float sc0 = exp2f(m0r - mn0), sc1 = exp2f(m1r - mn1);
        float sum0 = 0.f, sum1 = 0.f;
        int pr0 = wr + g, pr1 = wr + 8 + g;
        #pragma unroll
        for (int nj = 0; nj < 8; nj++) {
            __half2 x0 = __floats2half2_rn(sacc[nj][0] - mn0, sacc[nj][1] - mn0);
            __half2 x1 = __floats2half2_rn(sacc[nj][2] - mn1, sacc[nj][3] - mn1);
            unsigned e0 = h2ex2(*(unsigned*)&x0);
            unsigned e1 = h2ex2(*(unsigned*)&x1);
            float2 f0 = __half22float2(*(__half2*)&e0);
            float2 f1 = __half22float2(*(__half2*)&e1);
            sum0 += f0.x + f0.y;
            sum1 += f1.x + f1.y;
            *(unsigned*)(Pb + pr0 * 128 + ((nj ^ (pr0 & 7)) * 8 + 2 * t) * 2) = e0;
            *(unsigned*)(Pb + pr1 * 128 + ((nj ^ (pr1 & 7)) * 8 + 2 * t) * 2) = e1;
        }
        #pragma unroll
        for (int o = 1; o <= 2; o <<= 1) {
            sum0 += __shfl_xor_sync(0xffffffffu, sum0, o);
            sum1 += __shfl_xor_sync(0xffffffffu, sum1, o);
        }
        l0 = l0 * sc0 + sum0;
        l1 = l1 * sc1 + sum1;
        m0r = mn0; m1r = mn1;
        #pragma unroll
        for (int nj = 0; nj < 8; nj++) {
            oacc[nj][0] *= sc0; oacc[nj][1] *= sc0;
            oacc[nj][2] *= sc1; oacc[nj][3] *= sc1;
        }
        __syncwarp();   // P rows warp-local: STS -> LDSM ordering

        // O += P @ V
        #pragma unroll
        for (int j = 0; j < 4; j++) {
            unsigned pa[4];
            ldsm4(pa[0], pa[1], pa[2], pa[3], sQ + swz(wr + fr_row, 2 * j + fr_sg));
            #pragma unroll
            for (int nj2 = 0; nj2 < 4; nj2++) {
                unsigned r0, r1, r2, r3;
                ldsm4(r0, r1, r2, r3, sV + swz(nj2 * 16 + bn_row, 2 * j + bn_sg));
                unsigned b0[2] = {r0, r1}, b1[2] = {r2, r3};
                mma_f16(oacc[2 * nj2], pa, b0);
                mma_f16(oacc[2 * nj2 + 1], pa, b1);
            }
        }
        __syncthreads();   // readers done with buffer st before next prefetch into it
    }

    float inv0 = 1.f / l0, inv1 = 1.f / l1;
    int b = bh >> 4, hh = bh & 15;
    int tr0 = t0 + wr + g, tr1 = tr0 + 8;
    #pragma unroll
    for (int nj = 0; nj < 8; nj++) {
        int c = hh * DD + nj * 8 + 2 * t;
        *(__half2*)(out + (size_t)(b * TT + tr0) * CC + c) =
            __floats2half2_rn(oacc[nj][0] * inv0, oacc[nj][1] * inv0);
        *(__half2*)(out + (size_t)(b * TT + tr1) * CC + c) =
            __floats2half2_rn(oacc[nj][2] * inv1, oacc[nj][3] * inv1);
    }
}

// ============================================================
// launch
// ============================================================
extern "C" void kernel_launch(void* const* d_in, const int* in_sizes, int n_in,
                              void* d_out, int out_size) {
    const float* x      = (const float*)d_in[0];
    const float* wq     = (const float*)d_in[1];
    const float* wk     = (const float*)d_in[2];
    const float* wv     = (const float*)d_in[3];
    const float* w_proj = (const float*)d_in[4];
    const float* b_proj = (const float*)d_in[5];
    const float* w1     = (const float*)d_in[6];
    const float* b1     = (const float*)d_in[7];
    const float* w2     = (const float*)d_in[8];
    const float* b2     = (const float*)d_in[9];
    const float* g1     = (const float*)d_in[10];
    const float* be1    = (const float*)d_in[11];
    const float* g2     = (const float*)d_in[12];
    const float* be2    = (const float*)d_in[13];
    float* out = (float*)d_out;

    __half *h1, *q, *k, *v, *attn, *h2, *ff1;
    __half *wpt, *w1t, *w2t, *wqt, *wkt, *wvt;
    float *x1;
    cudaGetSymbolAddress((void**)&h1, g_h1);
    cudaGetSymbolAddress((void**)&q, g_q);
    cudaGetSymbolAddress((void**)&k, g_k);
    cudaGetSymbolAddress((void**)&v, g_v);
    cudaGetSymbolAddress((void**)&attn, g_attn);
    cudaGetSymbolAddress((void**)&x1, g_x1);
    cudaGetSymbolAddress((void**)&h2, g_h2);
    cudaGetSymbolAddress((void**)&ff1, g_ff1);
    cudaGetSymbolAddress((void**)&wpt, g_wpt);
    cudaGetSymbolAddress((void**)&w1t, g_w1t);
    cudaGetSymbolAddress((void**)&w2t, g_w2t);
    cudaGetSymbolAddress((void**)&wqt, g_wqt);
    cudaGetSymbolAddress((void**)&wkt, g_wkt);
    cudaGetSymbolAddress((void**)&wvt, g_wvt);

    cudaFuncSetAttribute(gemm_f16<false, false>, cudaFuncAttributeMaxDynamicSharedMemorySize, G_SMEM);
    cudaFuncSetAttribute(gemm_f16<true, true>,   cudaFuncAttributeMaxDynamicSharedMemorySize, G_SMEM);
    cudaFuncSetAttribute(qkv_f16, cudaFuncAttributeMaxDynamicSharedMemorySize, G_SMEM);
    cudaFuncSetAttribute(attn_f16, cudaFuncAttributeMaxDynamicSharedMemorySize, ATT_SMEM);

    // 0. weight transposes -> fp16 [N][K]
    transpose_big<<<9216, dim3(32, 8)>>>(w_proj, w1, w2, wpt, w1t, w2t);
    transpose_qkv<<<dim3(DD / 32, CC / 32, 3 * HH), dim3(32, 8)>>>(wq, wk, wv, wqt, wkt, wvt);
    // 1. LN1 -> fp16
    ln_kernel<<<MTOT, 256>>>(x, g1, be1, h1);
    // 2. QKV (merged; q pre-scaled by 0.125*log2e, v transposed)
    qkv_f16<<<dim3(MTOT / 128, 3 * (HH / 2)), 256, G_SMEM>>>(h1, wqt, wkt, wvt, q, k, v);
    // 3. attention -> fp16
    attn_f16<<<dim3(TT / 64, BBATCH * HH), 128, ATT_SMEM>>>(q, k, v, attn);
    // 4. proj + bias + residual -> x1 (fp32)
    gemm_f16<false, false><<<dim3(CC / 128, MTOT / 128), 256, G_SMEM>>>(
        attn, wpt, b_proj, x, x1, MTOT, CC, CC);
    // 5. LN2 -> fp16
    ln_kernel<<<MTOT, 256>>>(x1, g2, be2, h2);
    // 6. FF1 + bias + relu -> fp16
    gemm_f16<true, true><<<dim3(FFDIM / 128, MTOT / 128), 256, G_SMEM>>>(
        h2, w1t, b1, nullptr, ff1, MTOT, FFDIM, CC);
    // 7. FF2 + bias + residual -> out (fp32)
    gemm_f16<false, false><<<dim3(CC / 128, MTOT / 128), 256, G_SMEM>>>(
        ff1, w2t, b2, x1, out, MTOT, CC, FFDIM);
}

// round 17
// speedup vs baseline: 1.0295x; 1.0019x over previous
#include <cuda_runtime.h>
#include <cuda_fp16.h>
#include <math.h>
#include <stdint.h>

#define TT 2048
#define CC 1024
#define HH 16
#define DD 64
#define BBATCH 2
#define MTOT (BBATCH * TT)   // 4096
#define FFDIM (4 * CC)       // 4096
#define LOG2E 1.4426950408889634f

// -------- scratch (alloc-free) --------
__device__ __half g_h1[MTOT * CC];
__device__ __half g_q[MTOT * CC];     // (b,h,t,d), pre-scaled by 0.125*log2e
__device__ __half g_k[MTOT * CC];     // (b,h,t,d)
__device__ __half g_v[MTOT * CC];     // (b,h,d,t) transposed
__device__ __half g_attn[MTOT * CC];
__device__ float  g_x1[MTOT * CC];
__device__ __half g_h2[MTOT * CC];
__device__ __half g_ff1[MTOT * FFDIM];
// transposed fp16 weights [N][K]
__device__ __half g_wpt[CC * CC];
__device__ __half g_w1t[FFDIM * CC];
__device__ __half g_w2t[CC * FFDIM];
__device__ __half g_wqt[HH * DD * CC];
__device__ __half g_wkt[HH * DD * CC];
__device__ __half g_wvt[HH * DD * CC];

// -------- helpers --------
__device__ __forceinline__ void mma_f16(float* c, const unsigned* a, const unsigned* b) {
    asm volatile(
        "mma.sync.aligned.m16n8k16.row.col.f32.f16.f16.f32 "
        "{%0,%1,%2,%3}, {%4,%5,%6,%7}, {%8,%9}, {%0,%1,%2,%3};"
        : "+f"(c[0]), "+f"(c[1]), "+f"(c[2]), "+f"(c[3])
        : "r"(a[0]), "r"(a[1]), "r"(a[2]), "r"(a[3]), "r"(b[0]), "r"(b[1]));
}
__device__ __forceinline__ void cp16(uint32_t s, const void* g) {
    asm volatile("cp.async.ca.shared.global [%0], [%1], 16;" :: "r"(s), "l"(g));
}
__device__ __forceinline__ void cp_commit() { asm volatile("cp.async.commit_group;"); }
template <int N>
__device__ __forceinline__ void cp_wait() { asm volatile("cp.async.wait_group %0;" :: "n"(N)); }
__device__ __forceinline__ void ldsm4(unsigned& r0, unsigned& r1, unsigned& r2, unsigned& r3,
                                      uint32_t a) {
    asm volatile("ldmatrix.sync.aligned.m8n8.x4.shared.b16 {%0,%1,%2,%3}, [%4];"
                 : "=r"(r0), "=r"(r1), "=r"(r2), "=r"(r3) : "r"(a));
}
// packed fp16x2 2^x
__device__ __forceinline__ unsigned h2ex2(unsigned a) {
    unsigned d;
    asm("ex2.approx.f16x2 %0, %1;" : "=r"(d) : "r"(a));
    return d;
}
// 128B-pitch tile (64 halves/row): seg 0..7, conflict-free swizzle
__device__ __forceinline__ uint32_t swz(uint32_t r, uint32_t seg) {
    return r * 128 + ((seg ^ (r & 7)) * 16);
}

// ============================================================
// Merged big-weight transpose fp32 -> fp16 [N][K]
// ============================================================
__global__ void transpose_big(const float* __restrict__ wp, const float* __restrict__ w1,
                              const float* __restrict__ w2, __half* __restrict__ owp,
                              __half* __restrict__ ow1, __half* __restrict__ ow2) {
    __shared__ float t[32][33];
    int bid = blockIdx.x;
    const float* in;
    __half* out;
    int R, Cc, tile;
    if (bid < 1024)      { in = wp; out = owp; R = CC;    Cc = CC;    tile = bid; }
    else if (bid < 5120) { in = w1; out = ow1; R = CC;    Cc = FFDIM; tile = bid - 1024; }
    else                 { in = w2; out = ow2; R = FFDIM; Cc = CC;    tile = bid - 5120; }
    int nx = Cc >> 5;
    int c0 = (tile % nx) * 32, r0 = (tile / nx) * 32;
    int x = threadIdx.x, y = threadIdx.y;
    #pragma unroll
    for (int i = 0; i < 32; i += 8)
        t[y + i][x] = in[(size_t)(r0 + y + i) * Cc + c0 + x];
    __syncthreads();
    #pragma unroll
    for (int i = 0; i < 32; i += 8)
        out[(size_t)(c0 + y + i) * R + r0 + x] = __float2half(t[x][y + i]);
}

// Merged QKV weight transpose: z = which*HH + head
__global__ void transpose_qkv(const float* __restrict__ wq, const float* __restrict__ wk,
                              const float* __restrict__ wv, __half* __restrict__ oq,
                              __half* __restrict__ ok, __half* __restrict__ ov) {
    __shared__ float t[32][33];
    int which = blockIdx.z / HH, hd = blockIdx.z % HH;
    const float* ip = (which == 0 ? wq : (which == 1 ? wk : wv)) + (size_t)hd * CC * DD;
    __half* op = (which == 0 ? oq : (which == 1 ? ok : ov)) + (size_t)hd * CC * DD;
    int c0 = blockIdx.x * 32, r0 = blockIdx.y * 32;
    int x = threadIdx.x, y = threadIdx.y;
    #pragma unroll
    for (int i = 0; i < 32; i += 8)
        t[y + i][x] = ip[(size_t)(r0 + y + i) * DD + c0 + x];
    __syncthreads();
    #pragma unroll
    for (int i = 0; i < 32; i += 8)
        op[(size_t)(c0 + y + i) * CC + r0 + x] = __float2half(t[x][y + i]);
}

// ============================================================
// LayerNorm: fp32 in -> fp16 out
// ============================================================
__global__ void ln_kernel(const float* __restrict__ x, const float* __restrict__ g,
                          const float* __restrict__ b, __half* __restrict__ out) {
    __shared__ float red[8];
    __shared__ float s_mu, s_rstd;
    int row = blockIdx.x;
    int tid = threadIdx.x;
    const float* xr = x + (size_t)row * CC;

    float v0 = xr[tid], v1 = xr[tid + 256], v2 = xr[tid + 512], v3 = xr[tid + 768];
    float s = v0 + v1 + v2 + v3;
    #pragma unroll
    for (int o = 16; o > 0; o >>= 1) s += __shfl_xor_sync(0xffffffffu, s, o);
    if ((tid & 31) == 0) red[tid >> 5] = s;
    __syncthreads();
    if (tid == 0) {
        float t = 0.f;
        #pragma unroll
        for (int i = 0; i < 8; i++) t += red[i];
        s_mu = t * (1.0f / CC);
    }
    __syncthreads();
    float mu = s_mu;
    float d0 = v0 - mu, d1 = v1 - mu, d2 = v2 - mu, d3 = v3 - mu;
    float s2 = d0 * d0 + d1 * d1 + d2 * d2 + d3 * d3;
    #pragma unroll
    for (int o = 16; o > 0; o >>= 1) s2 += __shfl_xor_sync(0xffffffffu, s2, o);
    __syncthreads();
    if ((tid & 31) == 0) red[tid >> 5] = s2;
    __syncthreads();
    if (tid == 0) {
        float t = 0.f;
        #pragma unroll
        for (int i = 0; i < 8; i++) t += red[i];
        s_rstd = rsqrtf(t * (1.0f / CC) + 1e-5f);
    }
    __syncthreads();
    float rstd = s_rstd;
    __half* orow = out + (size_t)row * CC;
    orow[tid]       = __float2half(d0 * rstd * g[tid]       + b[tid]);
    orow[tid + 256] = __float2half(d1 * rstd * g[tid + 256] + b[tid + 256]);
    orow[tid + 512] = __float2half(d2 * rstd * g[tid + 512] + b[tid + 512]);
    orow[tid + 768] = __float2half(d3 * rstd * g[tid + 768] + b[tid + 768]);
}

// ============================================================
// fp16 GEMM (round-14 2-stage form — confirmed best)
// ============================================================
#define GT_BYTES (128 * 128)
#define G_SMEM (4 * GT_BYTES)

template <bool RELU, bool HALFOUT>
__global__ __launch_bounds__(256) void gemm_f16(
    const __half* __restrict__ A, const __half* __restrict__ Bt,
    const float* __restrict__ bias, const float* __restrict__ res,
    void* __restrict__ Cout, int M, int N, int K) {
    extern __shared__ char smx[];
    uint32_t sA = (uint32_t)__cvta_generic_to_shared(smx);
    uint32_t sB = sA + 2 * GT_BYTES;

    int tid = threadIdx.x;
    int warp = tid >> 5, lane = tid & 31;
    int g = lane >> 2, t = lane & 3;
    int wm = (warp >> 2) * 64, wn = (warp & 3) * 32;
    int m0 = blockIdx.y * 128, n0 = blockIdx.x * 128;

    float acc[4][4][4] = {};
    int a_row = wm + (lane & 7) + ((lane >> 3) & 1) * 8;
    int a_sg = lane >> 4;
    int b_row = wn + (lane & 7) + (lane >> 4) * 8;
    int b_sg = (lane >> 3) & 1;

    auto pre = [&](int st, int k0) {
        #pragma unroll
        for (int i = 0; i < 4; i++) {
            int ch = tid + 256 * i;
            int r = ch >> 3, c = ch & 7;
            cp16(sA + st * GT_BYTES + swz(r, c), A + (size_t)(m0 + r) * K + k0 + c * 8);
        }
        #pragma unroll
        for (int i = 0; i < 4; i++) {
            int ch = tid + 256 * i;
            int r = ch >> 3, c = ch & 7;
            cp16(sB + st * GT_BYTES + swz(r, c), Bt + (size_t)(n0 + r) * K + k0 + c * 8);
        }
        cp_commit();
    };

    pre(0, 0);
    int nk = K >> 6;
    for (int kk = 0; kk < nk; kk++) {
        int st = kk & 1;
        if (kk + 1 < nk) { pre(st ^ 1, (kk + 1) << 6); cp_wait<1>(); }
        else cp_wait<0>();
        __syncthreads();

        uint32_t sAs = sA + st * GT_BYTES;
        uint32_t sBs = sB + st * GT_BYTES;
        #pragma unroll
        for (int ks = 0; ks < 4; ks++) {
            unsigned af[4][4];
            #pragma unroll
            for (int mi = 0; mi < 4; mi++)
                ldsm4(af[mi][0], af[mi][1], af[mi][2], af[mi][3],
                      sAs + swz(a_row + mi * 16, 2 * ks + a_sg));
            #pragma unroll
            for (int nj2 = 0; nj2 < 2; nj2++) {
                unsigned r0, r1, r2, r3;
                ldsm4(r0, r1, r2, r3, sBs + swz(b_row + nj2 * 16, 2 * ks + b_sg));
                unsigned b0[2] = {r0, r1}, b1[2] = {r2, r3};
                #pragma unroll
                for (int mi = 0; mi < 4; mi++) {
                    mma_f16(acc[mi][2 * nj2],     af[mi], b0);
                    mma_f16(acc[mi][2 * nj2 + 1], af[mi], b1);
                }
            }
        }
        __syncthreads();
    }

    #pragma unroll
    for (int mi = 0; mi < 4; mi++) {
        #pragma unroll
        for (int nj = 0; nj < 4; nj++) {
            int c = n0 + wn + nj * 8 + 2 * t;
            int r0 = m0 + wm + mi * 16 + g;
            int r1 = r0 + 8;
            float2 o0 = {acc[mi][nj][0], acc[mi][nj][1]};
            float2 o1 = {acc[mi][nj][2], acc[mi][nj][3]};
            if (bias) {
                float2 bv = *(const float2*)(bias + c);
                o0.x += bv.x; o0.y += bv.y; o1.x += bv.x; o1.y += bv.y;
            }
            if (res) {
                float2 ra = *(const float2*)(res + (size_t)r0 * N + c);
                float2 rb = *(const float2*)(res + (size_t)r1 * N + c);
                o0.x += ra.x; o0.y += ra.y; o1.x += rb.x; o1.y += rb.y;
            }
            if (RELU) {
                o0.x = fmaxf(o0.x, 0.f); o0.y = fmaxf(o0.y, 0.f);
                o1.x = fmaxf(o1.x, 0.f); o1.y = fmaxf(o1.y, 0.f);
            }
            if (HALFOUT) {
                __half* C = (__half*)Cout;
                *(__half2*)(C + (size_t)r0 * N + c) = __floats2half2_rn(o0.x, o0.y);
                *(__half2*)(C + (size_t)r1 * N + c) = __floats2half2_rn(o1.x, o1.y);
            } else {
                float* C = (float*)Cout;
                *(float2*)(C + (size_t)r0 * N + c) = o0;
                *(float2*)(C + (size_t)r1 * N + c) = o1;
            }
        }
    }
}

// ============================================================
// Merged QKV GEMM (2-stage; Q scale = 0.125*log2e).
// V epilogue: smem-bounce transpose -> coalesced (b,h,d,t) stores.
// ============================================================
__global__ __launch_bounds__(256) void qkv_f16(
    const __half* __restrict__ h, const __half* __restrict__ wqt,
    const __half* __restrict__ wkt, const __half* __restrict__ wvt,
    __half* __restrict__ q, __half* __restrict__ k, __half* __restrict__ v) {
    extern __shared__ char smx[];
    uint32_t sA = (uint32_t)__cvta_generic_to_shared(smx);
    uint32_t sB = sA + 2 * GT_BYTES;

    int which = blockIdx.y >> 3;
    int hp = blockIdx.y & 7;
    const __half* Wt = (which == 0 ? wqt : (which == 1 ? wkt : wvt));
    __half* O = (which == 0 ? q : (which == 1 ? k : v));
    float oscale = (which == 0) ? 0.125f * LOG2E : 1.0f;

    int tid = threadIdx.x;
    int warp = tid >> 5, lane = tid & 31;
    int g = lane >> 2, t = lane & 3;
    int wm = (warp >> 2) * 64, wn = (warp & 3) * 32;
    int m0 = blockIdx.x * 128;

    float acc[4][4][4] = {};
    int a_row = wm + (lane & 7) + ((lane >> 3) & 1) * 8;
    int a_sg = lane >> 4;
    int b_row = wn + (lane & 7) + (lane >> 4) * 8;
    int b_sg = (lane >> 3) & 1;

    auto pre = [&](int st, int k0) {
        #pragma unroll
        for (int i = 0; i < 4; i++) {
            int ch = tid + 256 * i;
            int r = ch >> 3, c = ch & 7;
            cp16(sA + st * GT_BYTES + swz(r, c), h + (size_t)(m0 + r) * CC + k0 + c * 8);
        }
        #pragma unroll
        for (int i = 0; i < 4; i++) {
            int ch = tid + 256 * i;
            int r = ch >> 3, c = ch & 7;
            cp16(sB + st * GT_BYTES + swz(r, c),
                 Wt + (size_t)(hp * 128 + r) * CC + k0 + c * 8);
        }
        cp_commit();
    };

    pre(0, 0);
    int nk = CC >> 6;
    for (int kk = 0; kk < nk; kk++) {
        int st = kk & 1;
        if (kk + 1 < nk) { pre(st ^ 1, (kk + 1) << 6); cp_wait<1>(); }
        else cp_wait<0>();
        __syncthreads();

        uint32_t sAs = sA + st * GT_BYTES;
        uint32_t sBs = sB + st * GT_BYTES;
        #pragma unroll
        for (int ks = 0; ks < 4; ks++) {
            unsigned af[4][4];
            #pragma unroll
            for (int mi = 0; mi < 4; mi++)
                ldsm4(af[mi][0], af[mi][1], af[mi][2], af[mi][3],
                      sAs + swz(a_row + mi * 16, 2 * ks + a_sg));
            #pragma unroll
            for (int nj2 = 0; nj2 < 2; nj2++) {
                unsigned r0, r1, r2, r3;
                ldsm4(r0, r1, r2, r3, sBs + swz(b_row + nj2 * 16, 2 * ks + b_sg));
                unsigned b0[2] = {r0, r1}, b1[2] = {r2, r3};
                #pragma unroll
                for (int mi = 0; mi < 4; mi++) {
                    mma_f16(acc[mi][2 * nj2],     af[mi], b0);
                    mma_f16(acc[mi][2 * nj2 + 1], af[mi], b1);
                }
            }
        }
        __syncthreads();
    }

    if (which == 2) {
        // transpose through smem (free after k-loop barrier), coalesced store
        __half* Tr = (__half*)smx;   // 128 rows (c) x 136 pitch = 34.8KB
        #pragma unroll
        for (int mi = 0; mi < 4; mi++) {
            #pragma unroll
            for (int nj = 0; nj < 4; nj++) {
                int c = wn + nj * 8 + 2 * t;
                int ml0 = wm + mi * 16 + g, ml1 = ml0 + 8;
                Tr[c * 136 + ml0]       = __float2half(acc[mi][nj][0]);
                Tr[(c + 1) * 136 + ml0] = __float2half(acc[mi][nj][1]);
                Tr[c * 136 + ml1]       = __float2half(acc[mi][nj][2]);
                Tr[(c + 1) * 136 + ml1] = __float2half(acc[mi][nj][3]);
            }
        }
        __syncthreads();
        int b0 = m0 >> 11;
        int tbase = m0 & (TT - 1);
        int row = tid >> 1, part = tid & 1;     // 2 threads per c-row
        int head = 2 * hp + (row >> 6), d = row & 63;
        const uint4* src = (const uint4*)(Tr + row * 136 + part * 64);
        uint4* dst = (uint4*)(O + ((size_t)(b0 * HH + head) * DD + d) * TT + tbase + part * 64);
        #pragma unroll
        for (int i = 0; i < 8; i++) dst[i] = src[i];
    } else {
        #pragma unroll
        for (int mi = 0; mi < 4; mi++) {
            #pragma unroll
            for (int nj = 0; nj < 4; nj++) {
                int c = wn + nj * 8 + 2 * t;
                int head = 2 * hp + (c >> 6);
                int d = c & 63;
                int m0r = m0 + wm + mi * 16 + g;
                int m1r = m0r + 8;
                int b0 = m0r >> 11, t0i = m0r & (TT - 1);
                int b1 = m1r >> 11, t1i = m1r & (TT - 1);
                float a0 = acc[mi][nj][0] * oscale, a1 = acc[mi][nj][1] * oscale;
                float a2 = acc[mi][nj][2] * oscale, a3 = acc[mi][nj][3] * oscale;
                *(__half2*)(O + (((size_t)(b0 * HH + head) * TT + t0i) << 6) + d) =
                    __floats2half2_rn(a0, a1);
                *(__half2*)(O + (((size_t)(b1 * HH + head) * TT + t1i) << 6) + d) =
                    __floats2half2_rn(a2, a3);
            }
        }
    }
}

// ============================================================
// Flash attention (round-16 form: double-buffered K/V, ex2.f16x2)
// ============================================================
#define ATT_SMEM (16384 * 5)   // 81920

__global__ __launch_bounds__(128) void attn_f16(
    const __half* __restrict__ Q, const __half* __restrict__ K,
    const __half* __restrict__ V, __half* __restrict__ out) {
    extern __shared__ char smx[];
    uint32_t sQ = (uint32_t)__cvta_generic_to_shared(smx);
    uint32_t sK0 = sQ + 16384;
    uint32_t sV0 = sQ + 49152;
    char* Pb = smx;

    int bh = blockIdx.y;
    int t0 = (int)(gridDim.x - 1 - blockIdx.x) * 64;
    const __half* Qp = Q + (size_t)bh * TT * DD;
    const __half* Kp = K + (size_t)bh * TT * DD;
    const __half* Vp = V + (size_t)bh * TT * DD;

    int tid = threadIdx.x;
    int warp = tid >> 5, lane = tid & 31;
    int g = lane >> 2, t = lane & 3;
    int wr = warp * 16;

    int fr_row = (lane & 7) + ((lane >> 3) & 1) * 8;
    int fr_sg = lane >> 4;
    int bn_row = (lane & 7) + (lane >> 4) * 8;
    int bn_sg = (lane >> 3) & 1;

    #pragma unroll
    for (int i = 0; i < 4; i++) {
        int ch = tid + 128 * i;
        int r = ch >> 3, c = ch & 7;
        cp16(sQ + swz(r, c), Qp + (size_t)(t0 + r) * DD + c * 8);
    }
    cp_commit();
    cp_wait<0>();
    __syncthreads();
    unsigned qa[4][4];
    #pragma unroll
    for (int ks = 0; ks < 4; ks++)
        ldsm4(qa[ks][0], qa[ks][1], qa[ks][2], qa[ks][3],
              sQ + swz(wr + fr_row, 2 * ks + fr_sg));
    __syncthreads();

    auto preKV = [&](int st, int s0) {
        #pragma unroll
        for (int i = 0; i < 4; i++) {
            int ch = tid + 128 * i;
            int r = ch >> 3, c = ch & 7;
            cp16(sK0 + st * 16384 + swz(r, c), Kp + (size_t)(s0 + r) * DD + c * 8);
        }
        #pragma unroll
        for (int i = 0; i < 4; i++) {
            int ch = tid + 128 * i;
            int d = ch >> 3, c = ch & 7;
            cp16(sV0 + st * 16384 + swz(d, c), Vp + (size_t)d * TT + s0 + c * 8);
        }
        cp_commit();
    };

    float m0r = -1e30f, m1r = -1e30f, l0 = 0.f, l1 = 0.f;
    float oacc[8][4] = {};

    int ntiles = t0 / 64 + 1;
    preKV(0, 0);
    for (int it = 0; it < ntiles; it++) {
        int s0 = it * 64;
        int st = it & 1;
        if (it + 1 < ntiles) { preKV(st ^ 1, s0 + 64); cp_wait<1>(); }
        else cp_wait<0>();
        __syncthreads();
        uint32_t sK = sK0 + st * 16384;
        uint32_t sV = sV0 + st * 16384;

        float sacc[8][4] = {};
        #pragma unroll
        for (int ks = 0; ks < 4; ks++) {
            #pragma unroll
            for (int nj2 = 0; nj2 < 4; nj2++) {
                unsigned r0, r1, r2, r3;
                ldsm4(r0, r1, r2, r3, sK + swz(nj2 * 16 + bn_row, 2 * ks + bn_sg));
                unsigned b0[2] = {r0, r1}, b1[2] = {r2, r3};
                mma_f16(sacc[2 * nj2], qa[ks], b0);
                mma_f16(sacc[2 * nj2 + 1], qa[ks], b1);
            }
        }

        if (s0 == t0) {
            #pragma unroll
            for (int nj = 0; nj < 8; nj++) {
                int c0 = nj * 8 + 2 * t, c1 = c0 + 1;
                int r0 = wr + g, r1 = r0 + 8;
                if (c0 > r0) sacc[nj][0] = -1e30f;
                if (c1 > r0) sacc[nj][1] = -1e30f;
                if (c0 > r1) sacc[nj][2] = -1e30f;
                if (c1 > r1) sacc[nj][3] = -1e30f;
            }
        }

        float mt0 = -1e30f, mt1 = -1e30f;
        #pragma unroll
        for (int nj = 0; nj < 8; nj++) {
            mt0 = fmaxf(mt0, fmaxf(sacc[nj][0], sacc[nj][1]));
            mt1 = fmaxf(mt1, fmaxf(sacc[nj][2], sacc[nj][3]));
        }
        #pragma unroll
        for (int o = 1; o <= 2; o <<= 1) {
            mt0 = fmaxf(mt0, __shfl_xor_sync(0xffffffffu, mt0, o));
            mt1 = fmaxf(mt1, __shfl_xor_sync(0xffffffffu, mt1, o));
        }
        float mn0 = fmaxf(m0r, mt0), mn1 = fmaxf(m1r, mt1);
        float sc0 = exp2f(m0r - mn0), sc1 = exp2f(m1r - mn1);
        float sum0 = 0.f, sum1 = 0.f;
        int pr0 = wr + g, pr1 = wr + 8 + g;
        #pragma unroll
        for (int nj = 0; nj < 8; nj++) {
            __half2 x0 = __floats2half2_rn(sacc[nj][0] - mn0, sacc[nj][1] - mn0);
            __half2 x1 = __floats2half2_rn(sacc[nj][2] - mn1, sacc[nj][3] - mn1);
            unsigned e0 = h2ex2(*(unsigned*)&x0);
            unsigned e1 = h2ex2(*(unsigned*)&x1);
            float2 f0 = __half22float2(*(__half2*)&e0);
            float2 f1 = __half22float2(*(__half2*)&e1);
            sum0 += f0.x + f0.y;
            sum1 += f1.x + f1.y;
            *(unsigned*)(Pb + pr0 * 128 + ((nj ^ (pr0 & 7)) * 8 + 2 * t) * 2) = e0;
            *(unsigned*)(Pb + pr1 * 128 + ((nj ^ (pr1 & 7)) * 8 + 2 * t) * 2) = e1;
        }
        #pragma unroll
        for (int o = 1; o <= 2; o <<= 1) {
            sum0 += __shfl_xor_sync(0xffffffffu, sum0, o);
            sum1 += __shfl_xor_sync(0xffffffffu, sum1, o);
        }
        l0 = l0 * sc0 + sum0;
        l1 = l1 * sc1 + sum1;
        m0r = mn0; m1r = mn1;
        #pragma unroll
        for (int nj = 0; nj < 8; nj++) {
            oacc[nj][0] *= sc0; oacc[nj][1] *= sc0;
            oacc[nj][2] *= sc1; oacc[nj][3] *= sc1;
        }
        __syncwarp();

        #pragma unroll
        for (int j = 0; j < 4; j++) {
            unsigned pa[4];
            ldsm4(pa[0], pa[1], pa[2], pa[3], sQ + swz(wr + fr_row, 2 * j + fr_sg));
            #pragma unroll
            for (int nj2 = 0; nj2 < 4; nj2++) {
                unsigned r0, r1, r2, r3;
                ldsm4(r0, r1, r2, r3, sV + swz(nj2 * 16 + bn_row, 2 * j + bn_sg));
                unsigned b0[2] = {r0, r1}, b1[2] = {r2, r3};
                mma_f16(oacc[2 * nj2], pa, b0);
                mma_f16(oacc[2 * nj2 + 1], pa, b1);
            }
        }
        __syncthreads();
    }

    float inv0 = 1.f / l0, inv1 = 1.f / l1;
    int b = bh >> 4, hh = bh & 15;
    int tr0 = t0 + wr + g, tr1 = tr0 + 8;
    #pragma unroll
    for (int nj = 0; nj < 8; nj++) {
        int c = hh * DD + nj * 8 + 2 * t;
        *(__half2*)(out + (size_t)(b * TT + tr0) * CC + c) =
            __floats2half2_rn(oacc[nj][0] * inv0, oacc[nj][1] * inv0);
        *(__half2*)(out + (size_t)(b * TT + tr1) * CC + c) =
            __floats2half2_rn(oacc[nj][2] * inv1, oacc[nj][3] * inv1);
    }
}

// ============================================================
// launch
// ============================================================
extern "C" void kernel_launch(void* const* d_in, const int* in_sizes, int n_in,
                              void* d_out, int out_size) {
    const float* x      = (const float*)d_in[0];
    const float* wq     = (const float*)d_in[1];
    const float* wk     = (const float*)d_in[2];
    const float* wv     = (const float*)d_in[3];
    const float* w_proj = (const float*)d_in[4];
    const float* b_proj = (const float*)d_in[5];
    const float* w1     = (const float*)d_in[6];
    const float* b1     = (const float*)d_in[7];
    const float* w2     = (const float*)d_in[8];
    const float* b2     = (const float*)d_in[9];
    const float* g1     = (const float*)d_in[10];
    const float* be1    = (const float*)d_in[11];
    const float* g2     = (const float*)d_in[12];
    const float* be2    = (const float*)d_in[13];
    float* out = (float*)d_out;

    __half *h1, *q, *k, *v, *attn, *h2, *ff1;
    __half *wpt, *w1t, *w2t, *wqt, *wkt, *wvt;
    float *x1;
    cudaGetSymbolAddress((void**)&h1, g_h1);
    cudaGetSymbolAddress((void**)&q, g_q);
    cudaGetSymbolAddress((void**)&k, g_k);
    cudaGetSymbolAddress((void**)&v, g_v);
    cudaGetSymbolAddress((void**)&attn, g_attn);
    cudaGetSymbolAddress((void**)&x1, g_x1);
    cudaGetSymbolAddress((void**)&h2, g_h2);
    cudaGetSymbolAddress((void**)&ff1, g_ff1);
    cudaGetSymbolAddress((void**)&wpt, g_wpt);
    cudaGetSymbolAddress((void**)&w1t, g_w1t);
    cudaGetSymbolAddress((void**)&w2t, g_w2t);
    cudaGetSymbolAddress((void**)&wqt, g_wqt);
    cudaGetSymbolAddress((void**)&wkt, g_wkt);
    cudaGetSymbolAddress((void**)&wvt, g_wvt);

    cudaFuncSetAttribute(gemm_f16<false, false>, cudaFuncAttributeMaxDynamicSharedMemorySize, G_SMEM);
    cudaFuncSetAttribute(gemm_f16<true, true>,   cudaFuncAttributeMaxDynamicSharedMemorySize, G_SMEM);
    cudaFuncSetAttribute(qkv_f16, cudaFuncAttributeMaxDynamicSharedMemorySize, G_SMEM);
    cudaFuncSetAttribute(attn_f16, cudaFuncAttributeMaxDynamicSharedMemorySize, ATT_SMEM);

    // 0. weight transposes -> fp16 [N][K]
    transpose_big<<<9216, dim3(32, 8)>>>(w_proj, w1, w2, wpt, w1t, w2t);
    transpose_qkv<<<dim3(DD / 32, CC / 32, 3 * HH), dim3(32, 8)>>>(wq, wk, wv, wqt, wkt, wvt);
    // 1. LN1 -> fp16
    ln_kernel<<<MTOT, 256>>>(x, g1, be1, h1);
    // 2. QKV (merged; q pre-scaled by 0.125*log2e, v transposed via smem bounce)
    qkv_f16<<<dim3(MTOT / 128, 3 * (HH / 2)), 256, G_SMEM>>>(h1, wqt, wkt, wvt, q, k, v);
    // 3. attention -> fp16
    attn_f16<<<dim3(TT / 64, BBATCH * HH), 128, ATT_SMEM>>>(q, k, v, attn);
    // 4. proj + bias + residual -> x1 (fp32)
    gemm_f16<false, false><<<dim3(CC / 128, MTOT / 128), 256, G_SMEM>>>(
        attn, wpt, b_proj, x, x1, MTOT, CC, CC);
    // 5. LN2 -> fp16
    ln_kernel<<<MTOT, 256>>>(x1, g2, be2, h2);
    // 6. FF1 + bias + relu -> fp16
    gemm_f16<true, true><<<dim3(FFDIM / 128, MTOT / 128), 256, G_SMEM>>>(
        h2, w1t, b1, nullptr, ff1, MTOT, FFDIM, CC);
    // 7. FF2 + bias + residual -> out (fp32)
    gemm_f16<false, false><<<dim3(CC / 128, MTOT / 128), 256, G_SMEM>>>(
        ff1, w2t, b2, x1, out, MTOT, CC, FFDIM);
}